// round 16
// baseline (speedup 1.0000x reference)
#include <cuda_runtime.h>
#include <cuda_fp16.h>
#include <cstdint>
#include <cstddef>

#define N_TOK 4096
#define C_DIM 256
#define D_QK  32
#define BATCH 4
#define BLK_M 128
#define BLK_N 64
#define NKT   (N_TOK / BLK_N)
#define LOG2E 1.4426950408889634f

__device__ __half g_Qh[BATCH * N_TOK * D_QK];
__device__ __half g_Kh[BATCH * N_TOK * D_QK];
__device__ __half g_Kl[BATCH * N_TOK * D_QK];
__device__ __half g_Vh[BATCH * N_TOK * C_DIM];
__device__ __half g_xh[BATCH * C_DIM * N_TOK];
__device__ __half g_xl[BATCH * C_DIM * N_TOK];

// ------------------------------------------------------------- PTX helpers
__device__ __forceinline__ uint32_t smem_u32(const void* p) {
    uint32_t a;
    asm("{ .reg .u64 t; cvta.to.shared.u64 t, %1; cvt.u32.u64 %0, t; }"
        : "=r"(a) : "l"(p));
    return a;
}
__device__ __forceinline__ float fast_exp2(float x) {
    float r; asm("ex2.approx.ftz.f32 %0, %1;" : "=f"(r) : "f"(x)); return r;
}
__device__ __forceinline__ uint32_t packh2(float lo, float hi) {
    uint32_t d;
    asm("cvt.rn.f16x2.f32 %0, %1, %2;" : "=r"(d) : "f"(hi), "f"(lo));
    return d;
}
#define CPASYNC(dst, src) \
    asm volatile("cp.async.cg.shared.global [%0], [%1], 16;" \
                 :: "r"(dst), "l"(src))
#define CP_COMMIT() asm volatile("cp.async.commit_group;" ::: "memory")
#define CP_WAIT(n)  asm volatile("cp.async.wait_group %0;" :: "n"(n) : "memory")

__device__ __forceinline__ void ldsm_x4(uint32_t* d, uint32_t a) {
    asm volatile("ldmatrix.sync.aligned.m8n8.x4.shared.b16 {%0,%1,%2,%3}, [%4];"
                 : "=r"(d[0]), "=r"(d[1]), "=r"(d[2]), "=r"(d[3]) : "r"(a));
}
__device__ __forceinline__ void ldsm_x4t(uint32_t* d, uint32_t a) {
    asm volatile("ldmatrix.sync.aligned.m8n8.x4.trans.shared.b16 {%0,%1,%2,%3}, [%4];"
                 : "=r"(d[0]), "=r"(d[1]), "=r"(d[2]), "=r"(d[3]) : "r"(a));
}
__device__ __forceinline__ void mma16816(float* c, const uint32_t* a,
                                         uint32_t b0, uint32_t b1) {
    asm volatile(
        "mma.sync.aligned.m16n8k16.row.col.f32.f16.f16.f32 "
        "{%0,%1,%2,%3}, {%4,%5,%6,%7}, {%8,%9}, {%0,%1,%2,%3};"
        : "+f"(c[0]), "+f"(c[1]), "+f"(c[2]), "+f"(c[3])
        : "r"(a[0]), "r"(a[1]), "r"(a[2]), "r"(a[3]), "r"(b0), "r"(b1));
}
__device__ __forceinline__ void split_pack(float2 p, uint32_t& hi, uint32_t& lo) {
    __half hx = __float2half_rn(p.x), hy = __float2half_rn(p.y);
    __half2 h2 = __halves2half2(hx, hy);
    hi = *(uint32_t*)&h2;
    lo = packh2(p.x - __half2float(hx), p.y - __half2float(hy));
}

// ------------------------------------------------------------- attn smem
#define PAD_K   80
#define PAD_V   528
#define KBYTES  (BLK_N * PAD_K)            // 5120
#define VOFF    (2 * KBYTES)               // 10240
#define VBYTES  (BLK_N * PAD_V)            // 33792
#define BUF_BYTES (VOFF + VBYTES)          // 44032
#define SM_BUFS 10240                      // Qh region = 128*80
#define SM_ATTN (SM_BUFS + 3 * BUF_BYTES)  // 142336 (occ 1)

// ------------------------------------------------------------- proj smem
#define PX      144
#define PW      144
#define V_WB    (256 * PW)                 // 36864 (full 256 channels)
#define V_XO    V_WB
#define V_XLO   (V_XO + 32 * PX)           // 41472
#define V_PBUF  (V_XLO + 32 * PX)          // 46080
#define SM_PROJ (2 * V_PBUF)               // 92160

#define Q_WB    (64 * PW)
#define Q_XO    Q_WB
#define Q_XLO   (Q_XO + 32 * PX)
#define Q_PBUF  (Q_XLO + 32 * PX)          // 18432

// ==================== x -> fp16 hi/lo (wide) ============================
__global__ __launch_bounds__(256)
void cvt_x(const float* __restrict__ x) {
    const size_t total = (size_t)BATCH * C_DIM * N_TOK / 8;   // 8 floats/iter
    for (size_t i = blockIdx.x * 256 + threadIdx.x; i < total;
         i += (size_t)gridDim.x * 256) {
        float4 v0 = ((const float4*)x)[2 * i];
        float4 v1 = ((const float4*)x)[2 * i + 1];
        __half2 h0 = __floats2half2_rn(v0.x, v0.y);
        __half2 h1 = __floats2half2_rn(v0.z, v0.w);
        __half2 h2 = __floats2half2_rn(v1.x, v1.y);
        __half2 h3 = __floats2half2_rn(v1.z, v1.w);
        float2 f0 = __half22float2(h0), f1 = __half22float2(h1);
        float2 f2 = __half22float2(h2), f3 = __half22float2(h3);
        __half2 l0 = __floats2half2_rn(v0.x - f0.x, v0.y - f0.y);
        __half2 l1 = __floats2half2_rn(v0.z - f1.x, v0.w - f1.y);
        __half2 l2 = __floats2half2_rn(v1.x - f2.x, v1.y - f2.y);
        __half2 l3 = __floats2half2_rn(v1.z - f3.x, v1.w - f3.y);
        uint4 hi = make_uint4(*(uint32_t*)&h0, *(uint32_t*)&h1,
                              *(uint32_t*)&h2, *(uint32_t*)&h3);
        uint4 lo = make_uint4(*(uint32_t*)&l0, *(uint32_t*)&l1,
                              *(uint32_t*)&l2, *(uint32_t*)&l3);
        ((uint4*)g_xh)[i] = hi;
        ((uint4*)g_xl)[i] = lo;
    }
}

// ============ fused projections: y==0 -> V (256 ch), y==1 -> Q+K ===========
__global__ __launch_bounds__(256)
void proj_fused(const float* __restrict__ Wq, const float* __restrict__ bq,
                const float* __restrict__ Wk, const float* __restrict__ bk,
                const float* __restrict__ Wv, const float* __restrict__ bv) {
    extern __shared__ char smc[];
    const uint32_t sb = smem_u32(smc);
    const int tid = threadIdx.x;
    const int w = tid >> 5, lane = tid & 31;
    const int g = lane >> 2, c4 = lane & 3;
    const int b = blockIdx.z;
    const int n0 = blockIdx.x * 64;

    const int ls = lane & 15, lr = ls & 7, lsel = ls >> 3;
    const uint32_t xoff = (uint32_t)((lsel * 8 + lr) * PX + (lane >> 4) * 16);

    const __half* xh = g_xh + (size_t)b * C_DIM * N_TOK + n0;
    const __half* xl = g_xl + (size_t)b * C_DIM * N_TOK + n0;

    if (blockIdx.y == 0) {
        // ---------------- V projection: all 256 channels ----------------
        auto issue = [&](int ks, int bufi) {
            const int k0 = ks * 32;
            uint32_t base = sb + bufi * V_PBUF;
#pragma unroll
            for (int i = 0; i < 8; i++) {
                int idx = i * 256 + tid, row = idx >> 3, cc = idx & 7;
                CPASYNC(base + row * PW + cc * 16,
                        Wv + (size_t)row * C_DIM + k0 + cc * 4);
            }
            {
                int row = tid >> 3, cc = tid & 7;
                CPASYNC(base + V_XO + row * PX + cc * 16,
                        xh + (size_t)(k0 + row) * N_TOK + cc * 8);
                CPASYNC(base + V_XLO + row * PX + cc * 16,
                        xl + (size_t)(k0 + row) * N_TOK + cc * 8);
            }
            CP_COMMIT();
        };

        issue(0, 0);
        issue(1, 1);

        float c[2][8][4];
#pragma unroll
        for (int f = 0; f < 2; f++)
#pragma unroll
            for (int n = 0; n < 8; n++)
#pragma unroll
                for (int j = 0; j < 4; j++) c[f][n][j] = 0.f;

        for (int ks = 0; ks < 8; ks++) {
            CP_WAIT(1);
            __syncthreads();
            const char* bp = smc + (ks & 1) * V_PBUF;
            const uint32_t xb32 = sb + (ks & 1) * V_PBUF + V_XO + xoff;

#pragma unroll
            for (int kk = 0; kk < 2; kk++) {
                uint32_t ah[2][4], al[2][4];
#pragma unroll
                for (int f = 0; f < 2; f++) {
                    const char* wr = bp + (f * 128 + 16 * w + g) * PW
                                     + kk * 64 + c4 * 8;
                    float2 p00 = *(const float2*)wr;
                    float2 p10 = *(const float2*)(wr + 8 * PW);
                    float2 p01 = *(const float2*)(wr + 32);
                    float2 p11 = *(const float2*)(wr + 8 * PW + 32);
                    split_pack(p00, ah[f][0], al[f][0]);
                    split_pack(p10, ah[f][1], al[f][1]);
                    split_pack(p01, ah[f][2], al[f][2]);
                    split_pack(p11, ah[f][3], al[f][3]);
                }
#pragma unroll
                for (int nf = 0; nf < 8; nf += 2) {
                    uint32_t bh[4], bl[4];
                    uint32_t a = xb32 + kk * (16 * PX) + nf * 16;
                    ldsm_x4t(bh, a);
                    ldsm_x4t(bl, a + (V_XLO - V_XO));
#pragma unroll
                    for (int f = 0; f < 2; f++) {
                        mma16816(c[f][nf], ah[f], bh[0], bh[1]);
                        mma16816(c[f][nf], ah[f], bl[0], bl[1]);
                        mma16816(c[f][nf], al[f], bh[0], bh[1]);
                        mma16816(c[f][nf + 1], ah[f], bh[2], bh[3]);
                        mma16816(c[f][nf + 1], ah[f], bl[2], bl[3]);
                        mma16816(c[f][nf + 1], al[f], bh[2], bh[3]);
                    }
                }
            }
            __syncthreads();
            if (ks + 2 < 8) issue(ks + 2, ks & 1);
            else CP_COMMIT();
        }

        float bias[2][2];
#pragma unroll
        for (int f = 0; f < 2; f++) {
            bias[f][0] = bv[f * 128 + 16 * w + g];
            bias[f][1] = bv[f * 128 + 16 * w + g + 8];
        }
        __syncthreads();
        __half* st = (__half*)smc;               // [64 n][264 m]
#pragma unroll
        for (int f = 0; f < 2; f++)
#pragma unroll
            for (int nf = 0; nf < 8; nf++) {
                int n = nf * 8 + 2 * c4;
                int m = f * 128 + 16 * w + g;
                st[n * 264 + m]           = __float2half_rn(c[f][nf][0] + bias[f][0]);
                st[(n + 1) * 264 + m]     = __float2half_rn(c[f][nf][1] + bias[f][0]);
                st[n * 264 + m + 8]       = __float2half_rn(c[f][nf][2] + bias[f][1]);
                st[(n + 1) * 264 + m + 8] = __float2half_rn(c[f][nf][3] + bias[f][1]);
            }
        __syncthreads();
#pragma unroll
        for (int i = 0; i < 8; i++) {
            int idx = i * 256 + tid, n = idx >> 5, cc = idx & 31;
            *(uint4*)&g_Vh[((size_t)b * N_TOK + n0 + n) * C_DIM + cc * 8] =
                *(const uint4*)&st[n * 264 + cc * 8];
        }
    } else {
        // ---------------- Q+K projection ----------------
        const int mg = w & 3, nh = w >> 2;

        auto issue = [&](int ks, int bufi) {
            const int k0 = ks * 32;
            uint32_t base = sb + bufi * Q_PBUF;
#pragma unroll
            for (int i = 0; i < 2; i++) {
                int idx = i * 256 + tid, row = idx >> 3, cc = idx & 7;
                const float* src = (row < 32)
                    ? Wq + (size_t)row * C_DIM + k0 + cc * 4
                    : Wk + (size_t)(row - 32) * C_DIM + k0 + cc * 4;
                CPASYNC(base + row * PW + cc * 16, src);
            }
            {
                int row = tid >> 3, cc = tid & 7;
                CPASYNC(base + Q_XO + row * PX + cc * 16,
                        xh + (size_t)(k0 + row) * N_TOK + cc * 8);
                CPASYNC(base + Q_XLO + row * PX + cc * 16,
                        xl + (size_t)(k0 + row) * N_TOK + cc * 8);
            }
            CP_COMMIT();
        };

        issue(0, 0);
        issue(1, 1);

        float c[4][4];
#pragma unroll
        for (int n = 0; n < 4; n++)
#pragma unroll
            for (int j = 0; j < 4; j++) c[n][j] = 0.f;

        for (int ks = 0; ks < 8; ks++) {
            CP_WAIT(1);
            __syncthreads();
            const char* bp = smc + (ks & 1) * Q_PBUF;
            const uint32_t xb32 = sb + (ks & 1) * Q_PBUF + Q_XO + xoff;

#pragma unroll
            for (int kk = 0; kk < 2; kk++) {
                const char* wr = bp + (16 * mg + g) * PW + kk * 64 + c4 * 8;
                float2 p00 = *(const float2*)wr;
                float2 p10 = *(const float2*)(wr + 8 * PW);
                float2 p01 = *(const float2*)(wr + 32);
                float2 p11 = *(const float2*)(wr + 8 * PW + 32);
                uint32_t ah[4], al[4];
                split_pack(p00, ah[0], al[0]);
                split_pack(p10, ah[1], al[1]);
                split_pack(p01, ah[2], al[2]);
                split_pack(p11, ah[3], al[3]);
#pragma unroll
                for (int j = 0; j < 4; j += 2) {
                    uint32_t bh[4], bl[4];
                    uint32_t a = xb32 + kk * (16 * PX) + (4 * nh + j) * 16;
                    ldsm_x4t(bh, a);
                    ldsm_x4t(bl, a + (Q_XLO - Q_XO));
                    mma16816(c[j], ah, bh[0], bh[1]);
                    mma16816(c[j], ah, bl[0], bl[1]);
                    mma16816(c[j], al, bh[0], bh[1]);
                    mma16816(c[j + 1], ah, bh[2], bh[3]);
                    mma16816(c[j + 1], ah, bl[2], bl[3]);
                    mma16816(c[j + 1], al, bh[2], bh[3]);
                }
            }
            __syncthreads();
            if (ks + 2 < 8) issue(ks + 2, ks & 1);
            else CP_COMMIT();
        }

        const int m = 16 * mg + g;
        const bool isQ = (mg < 2);
        const int col0 = isQ ? m : m - 32;
        const int col1 = col0 + 8;
        const float bias0 = isQ ? bq[col0] : bk[col0];
        const float bias1 = isQ ? bq[col1] : bk[col1];
        const float sc = isQ ? LOG2E : 1.f;

#pragma unroll
        for (int j = 0; j < 4; j++) {
            int n = n0 + (4 * nh + j) * 8 + 2 * c4;
            float v[4] = { (c[j][0] + bias0) * sc, (c[j][1] + bias0) * sc,
                           (c[j][2] + bias1) * sc, (c[j][3] + bias1) * sc };
            size_t i00 = ((size_t)b * N_TOK + n) * D_QK;
            size_t i01 = ((size_t)b * N_TOK + n + 1) * D_QK;
#pragma unroll
            for (int t = 0; t < 4; t++) {
                size_t di = ((t & 1) ? i01 : i00) + ((t < 2) ? col0 : col1);
                __half hv = __float2half_rn(v[t]);
                if (isQ) {
                    g_Qh[di] = hv;
                } else {
                    g_Kh[di] = hv;
                    g_Kl[di] = __float2half_rn(v[t] - __half2float(hv));
                }
            }
        }
    }
}

// ===== flash attention: R14 core + fused K hi/lo ldsm_x4 ===================
__global__ __launch_bounds__(256, 1)
void attn_hmma(float* __restrict__ out) {
    extern __shared__ char smc[];
    const uint32_t sb = smem_u32(smc);
    const int tid = threadIdx.x;
    const int w = tid >> 5, lane = tid & 31;
    const int g = lane >> 2, c4 = lane & 3;
    const int b = blockIdx.y, m0 = blockIdx.x * BLK_M;

    // ---- stage Qh tile ----
    {
        const __half* Qh = g_Qh + ((size_t)b * N_TOK + m0) * D_QK;
#pragma unroll
        for (int i = 0; i < 2; i++) {
            int idx = i * 256 + tid;
            int row = idx >> 2, cc = idx & 3;
            CPASYNC(sb + row * PAD_K + cc * 16, Qh + row * D_QK + cc * 8);
        }
        CP_COMMIT();
        CP_WAIT(0);
        __syncthreads();
    }
    uint32_t qh[2][4];
    {
        uint32_t qoff = (uint32_t)((16 * w + ((lane >> 3) & 1) * 8 + (lane & 7)) * PAD_K
                                   + (lane >> 4) * 16);
#pragma unroll
        for (int kk = 0; kk < 2; kk++)
            ldsm_x4(qh[kk], sb + qoff + kk * 32);
    }
    __syncthreads();

    const __half* Kh = g_Kh + (size_t)b * N_TOK * D_QK;
    const __half* Kl = g_Kl + (size_t)b * N_TOK * D_QK;
    const __half* Vh = g_Vh + (size_t)b * N_TOK * C_DIM;

    const int ls = lane & 15, lr = ls & 7, lsel = ls >> 3;
    // lanes 0-15 -> Kh fragment addresses; lanes 16-31 -> Kl (same layout + KBYTES)
    const uint32_t kbx = (uint32_t)(lr * PAD_K + lsel * 16 + (lane >> 4) * KBYTES);
    const uint32_t vb = (uint32_t)(VOFF + (lsel * 8 + lr) * PAD_V + (lane >> 4) * 16);

    auto issue_tile = [&](int kt0, uint32_t bs_) {
        {
            int row = tid >> 2, cc = tid & 3;
            uint32_t dst = bs_ + row * PAD_K + cc * 16;
            CPASYNC(dst, Kh + (kt0 + row) * D_QK + cc * 8);
            CPASYNC(dst + (uint32_t)KBYTES, Kl + (kt0 + row) * D_QK + cc * 8);
        }
#pragma unroll
        for (int i = 0; i < 8; i++) {
            int idx = i * 256 + tid;
            int row = idx >> 5, cc = idx & 31;
            CPASYNC(bs_ + VOFF + row * PAD_V + cc * 16,
                    Vh + (size_t)(kt0 + row) * C_DIM + cc * 8);
        }
        CP_COMMIT();
    };

    issue_tile(0, sb + SM_BUFS);
    issue_tile(BLK_N, sb + SM_BUFS + BUF_BYTES);

    float o[32][4];
#pragma unroll
    for (int n = 0; n < 32; n++)
#pragma unroll
        for (int j = 0; j < 4; j++) o[n][j] = 0.f;
    float m2l = -1e30f, m2h = -1e30f, llo = 0.f, lhi = 0.f;

    int b3 = 0;
    for (int kt = 0; kt < NKT; kt++) {
        CP_WAIT(1);
        __syncthreads();

        int i3 = b3 + 2; if (i3 >= 3) i3 -= 3;
        if (kt + 2 < NKT)
            issue_tile((kt + 2) * BLK_N, sb + SM_BUFS + i3 * BUF_BYTES);
        else
            CP_COMMIT();

        const uint32_t bs_ = sb + SM_BUFS + b3 * BUF_BYTES;

        // ----- S = Q K^T : 2-term, fused hi/lo ldsm_x4 -----
        float sf[8][4];
#pragma unroll
        for (int n = 0; n < 8; n++)
#pragma unroll
            for (int j = 0; j < 4; j++) sf[n][j] = 0.f;

#pragma unroll
        for (int n = 0; n < 8; n++) {
#pragma unroll
            for (int kk = 0; kk < 2; kk++) {
                uint32_t kd[4];
                ldsm_x4(kd, bs_ + kbx + n * (8 * PAD_K) + kk * 32);
                mma16816(sf[n], qh[kk], kd[0], kd[1]);   // Qh * Kh
                mma16816(sf[n], qh[kk], kd[2], kd[3]);   // Qh * Kl
            }
        }

        // ----- online softmax -----
        float rml = -1e30f, rmh = -1e30f;
#pragma unroll
        for (int n = 0; n < 8; n++) {
            rml = fmaxf(rml, fmaxf(sf[n][0], sf[n][1]));
            rmh = fmaxf(rmh, fmaxf(sf[n][2], sf[n][3]));
        }
#pragma unroll
        for (int off = 1; off <= 2; off <<= 1) {
            rml = fmaxf(rml, __shfl_xor_sync(0xffffffffu, rml, off));
            rmh = fmaxf(rmh, __shfl_xor_sync(0xffffffffu, rmh, off));
        }
        float mnl = fmaxf(m2l, rml), mnh = fmaxf(m2h, rmh);
        bool ch = (mnl != m2l) || (mnh != m2h);
        if (__any_sync(0xffffffffu, ch)) {
            float sl = fast_exp2(m2l - mnl), sh = fast_exp2(m2h - mnh);
            llo *= sl; lhi *= sh;
#pragma unroll
            for (int n = 0; n < 32; n++) {
                o[n][0] *= sl; o[n][1] *= sl;
                o[n][2] *= sh; o[n][3] *= sh;
            }
        }
        m2l = mnl; m2h = mnh;

#pragma unroll
        for (int n = 0; n < 8; n++) {
            sf[n][0] = fast_exp2(sf[n][0] - mnl);
            sf[n][1] = fast_exp2(sf[n][1] - mnl);
            sf[n][2] = fast_exp2(sf[n][2] - mnh);
            sf[n][3] = fast_exp2(sf[n][3] - mnh);
            llo += sf[n][0] + sf[n][1];
            lhi += sf[n][2] + sf[n][3];
        }

        // ----- O += P V -----
#pragma unroll
        for (int kk = 0; kk < 4; kk++) {
            uint32_t pa[4];
            pa[0] = packh2(sf[2 * kk][0],     sf[2 * kk][1]);
            pa[1] = packh2(sf[2 * kk][2],     sf[2 * kk][3]);
            pa[2] = packh2(sf[2 * kk + 1][0], sf[2 * kk + 1][1]);
            pa[3] = packh2(sf[2 * kk + 1][2], sf[2 * kk + 1][3]);
            uint32_t va = bs_ + vb + kk * (16 * PAD_V);
#pragma unroll
            for (int n = 0; n < 32; n += 2) {
                uint32_t bf[4];
                ldsm_x4t(bf, va + n * 16);
                mma16816(o[n],     pa, bf[0], bf[1]);
                mma16816(o[n + 1], pa, bf[2], bf[3]);
            }
        }

        if (++b3 == 3) b3 = 0;
    }

    // ---- epilogue ----
#pragma unroll
    for (int off = 1; off <= 2; off <<= 1) {
        llo += __shfl_xor_sync(0xffffffffu, llo, off);
        lhi += __shfl_xor_sync(0xffffffffu, lhi, off);
    }
    const float il = 1.f / llo, ih = 1.f / lhi;
    const int tok_lo = m0 + 16 * w + g, tok_hi = tok_lo + 8;
    float* ob = out + (size_t)b * C_DIM * N_TOK;
#pragma unroll
    for (int n = 0; n < 32; n++) {
        int ch0 = 8 * n + 2 * c4;
        ob[(size_t)ch0 * N_TOK + tok_lo]       = o[n][0] * il;
        ob[(size_t)(ch0 + 1) * N_TOK + tok_lo] = o[n][1] * il;
        ob[(size_t)ch0 * N_TOK + tok_hi]       = o[n][2] * ih;
        ob[(size_t)(ch0 + 1) * N_TOK + tok_hi] = o[n][3] * ih;
    }
}

// ---------------- launch ----------------
extern "C" void kernel_launch(void* const* d_in, const int* in_sizes, int n_in,
                              void* d_out, int out_size) {
    (void)in_sizes; (void)n_in; (void)out_size;
    const float* x  = (const float*)d_in[0];
    const float* Wq = (const float*)d_in[1];
    const float* bq = (const float*)d_in[2];
    const float* Wk = (const float*)d_in[3];
    const float* bk = (const float*)d_in[4];
    const float* Wv = (const float*)d_in[5];
    const float* bv = (const float*)d_in[6];
    float* out = (float*)d_out;

    cudaFuncSetAttribute(attn_hmma, cudaFuncAttributeMaxDynamicSharedMemorySize,
                         SM_ATTN);
    cudaFuncSetAttribute(proj_fused, cudaFuncAttributeMaxDynamicSharedMemorySize,
                         SM_PROJ);

    cvt_x<<<1024, 256>>>(x);

    dim3 gp(N_TOK / 64, 2, BATCH);
    proj_fused<<<gp, 256, SM_PROJ>>>(Wq, bq, Wk, bk, Wv, bv);

    dim3 ga(N_TOK / BLK_M, BATCH);
    attn_hmma<<<ga, 256, SM_ATTN>>>(out);
}

// round 17
// speedup vs baseline: 1.0331x; 1.0331x over previous
#include <cuda_runtime.h>
#include <cuda_fp16.h>
#include <cstdint>
#include <cstddef>

#define N_TOK 4096
#define C_DIM 256
#define D_QK  32
#define BATCH 4
#define BLK_M 128
#define BLK_N 64
#define NKT   (N_TOK / BLK_N)
#define LOG2E 1.4426950408889634f

__device__ __half g_Qh[BATCH * N_TOK * D_QK];
__device__ __half g_Kh[BATCH * N_TOK * D_QK];
__device__ __half g_Kl[BATCH * N_TOK * D_QK];
__device__ __half g_Vh[BATCH * N_TOK * C_DIM];
__device__ __half g_xh[BATCH * C_DIM * N_TOK];
__device__ __half g_xl[BATCH * C_DIM * N_TOK];

// ------------------------------------------------------------- PTX helpers
__device__ __forceinline__ uint32_t smem_u32(const void* p) {
    uint32_t a;
    asm("{ .reg .u64 t; cvta.to.shared.u64 t, %1; cvt.u32.u64 %0, t; }"
        : "=r"(a) : "l"(p));
    return a;
}
__device__ __forceinline__ float fast_exp2(float x) {
    float r; asm("ex2.approx.ftz.f32 %0, %1;" : "=f"(r) : "f"(x)); return r;
}
__device__ __forceinline__ uint32_t packh2(float lo, float hi) {
    uint32_t d;
    asm("cvt.rn.f16x2.f32 %0, %1, %2;" : "=r"(d) : "f"(hi), "f"(lo));
    return d;
}
#define CPASYNC(dst, src) \
    asm volatile("cp.async.cg.shared.global [%0], [%1], 16;" \
                 :: "r"(dst), "l"(src))
#define CP_COMMIT() asm volatile("cp.async.commit_group;" ::: "memory")
#define CP_WAIT(n)  asm volatile("cp.async.wait_group %0;" :: "n"(n) : "memory")

__device__ __forceinline__ void ldsm_x4(uint32_t* d, uint32_t a) {
    asm volatile("ldmatrix.sync.aligned.m8n8.x4.shared.b16 {%0,%1,%2,%3}, [%4];"
                 : "=r"(d[0]), "=r"(d[1]), "=r"(d[2]), "=r"(d[3]) : "r"(a));
}
__device__ __forceinline__ void ldsm_x4t(uint32_t* d, uint32_t a) {
    asm volatile("ldmatrix.sync.aligned.m8n8.x4.trans.shared.b16 {%0,%1,%2,%3}, [%4];"
                 : "=r"(d[0]), "=r"(d[1]), "=r"(d[2]), "=r"(d[3]) : "r"(a));
}
__device__ __forceinline__ void mma16816(float* c, const uint32_t* a,
                                         uint32_t b0, uint32_t b1) {
    asm volatile(
        "mma.sync.aligned.m16n8k16.row.col.f32.f16.f16.f32 "
        "{%0,%1,%2,%3}, {%4,%5,%6,%7}, {%8,%9}, {%0,%1,%2,%3};"
        : "+f"(c[0]), "+f"(c[1]), "+f"(c[2]), "+f"(c[3])
        : "r"(a[0]), "r"(a[1]), "r"(a[2]), "r"(a[3]), "r"(b0), "r"(b1));
}
__device__ __forceinline__ void split_pack(float2 p, uint32_t& hi, uint32_t& lo) {
    __half hx = __float2half_rn(p.x), hy = __float2half_rn(p.y);
    __half2 h2 = __halves2half2(hx, hy);
    hi = *(uint32_t*)&h2;
    lo = packh2(p.x - __half2float(hx), p.y - __half2float(hy));
}

// ------------------------------------------------------------- attn smem
#define PAD_K   80
#define PAD_V   528
#define KBYTES  (BLK_N * PAD_K)            // 5120
#define VOFF    (2 * KBYTES)               // 10240
#define VBYTES  (BLK_N * PAD_V)            // 33792
#define BUF_BYTES (VOFF + VBYTES)          // 44032
#define SM_BUFS 10240                      // Qh region = 128*80
#define SM_ATTN (SM_BUFS + 3 * BUF_BYTES)  // 142336 (occ 1)

// ------------------------------------------------------------- proj smem
#define PX      144
#define PW      144
#define V_WB    (128 * PW)
#define V_XO    V_WB
#define V_XLO   (V_XO + 32 * PX)
#define V_PBUF  (V_XLO + 32 * PX)
#define SM_PROJ (2 * V_PBUF)               // 55296

#define Q_WB    (64 * PW)
#define Q_XO    Q_WB
#define Q_XLO   (Q_XO + 32 * PX)
#define Q_PBUF  (Q_XLO + 32 * PX)

// ==================== x -> fp16 hi/lo (wide) ============================
__global__ __launch_bounds__(256)
void cvt_x(const float* __restrict__ x) {
    const size_t total = (size_t)BATCH * C_DIM * N_TOK / 8;
    for (size_t i = blockIdx.x * 256 + threadIdx.x; i < total;
         i += (size_t)gridDim.x * 256) {
        float4 v0 = ((const float4*)x)[2 * i];
        float4 v1 = ((const float4*)x)[2 * i + 1];
        __half2 h0 = __floats2half2_rn(v0.x, v0.y);
        __half2 h1 = __floats2half2_rn(v0.z, v0.w);
        __half2 h2 = __floats2half2_rn(v1.x, v1.y);
        __half2 h3 = __floats2half2_rn(v1.z, v1.w);
        float2 f0 = __half22float2(h0), f1 = __half22float2(h1);
        float2 f2 = __half22float2(h2), f3 = __half22float2(h3);
        __half2 l0 = __floats2half2_rn(v0.x - f0.x, v0.y - f0.y);
        __half2 l1 = __floats2half2_rn(v0.z - f1.x, v0.w - f1.y);
        __half2 l2 = __floats2half2_rn(v1.x - f2.x, v1.y - f2.y);
        __half2 l3 = __floats2half2_rn(v1.z - f3.x, v1.w - f3.y);
        uint4 hi = make_uint4(*(uint32_t*)&h0, *(uint32_t*)&h1,
                              *(uint32_t*)&h2, *(uint32_t*)&h3);
        uint4 lo = make_uint4(*(uint32_t*)&l0, *(uint32_t*)&l1,
                              *(uint32_t*)&l2, *(uint32_t*)&l3);
        ((uint4*)g_xh)[i] = hi;
        ((uint4*)g_xl)[i] = lo;
    }
}

// ============ fused projections: y<2 -> V halves, y==2 -> Q+K ==============
__global__ __launch_bounds__(256)
void proj_fused(const float* __restrict__ Wq, const float* __restrict__ bq,
                const float* __restrict__ Wk, const float* __restrict__ bk,
                const float* __restrict__ Wv, const float* __restrict__ bv) {
    extern __shared__ char smc[];
    const uint32_t sb = smem_u32(smc);
    const int tid = threadIdx.x;
    const int w = tid >> 5, lane = tid & 31;
    const int g = lane >> 2, c4 = lane & 3;
    const int b = blockIdx.z;
    const int n0 = blockIdx.x * 64;

    const int ls = lane & 15, lr = ls & 7, lsel = ls >> 3;
    const uint32_t xoff = (uint32_t)((lsel * 8 + lr) * PX + (lane >> 4) * 16);

    const __half* xh = g_xh + (size_t)b * C_DIM * N_TOK + n0;
    const __half* xl = g_xl + (size_t)b * C_DIM * N_TOK + n0;

    if (blockIdx.y < 2) {
        // ---------------- V projection half ----------------
        const int m0 = blockIdx.y * 128;

        auto issue = [&](int ks, int bufi) {
            const int k0 = ks * 32;
            uint32_t base = sb + bufi * V_PBUF;
#pragma unroll
            for (int i = 0; i < 4; i++) {
                int idx = i * 256 + tid, row = idx >> 3, cc = idx & 7;
                CPASYNC(base + row * PW + cc * 16,
                        Wv + (size_t)(m0 + row) * C_DIM + k0 + cc * 4);
            }
            {
                int row = tid >> 3, cc = tid & 7;
                CPASYNC(base + V_XO + row * PX + cc * 16,
                        xh + (size_t)(k0 + row) * N_TOK + cc * 8);
                CPASYNC(base + V_XLO + row * PX + cc * 16,
                        xl + (size_t)(k0 + row) * N_TOK + cc * 8);
            }
            CP_COMMIT();
        };

        issue(0, 0);
        issue(1, 1);

        float c[8][4];
#pragma unroll
        for (int n = 0; n < 8; n++)
#pragma unroll
            for (int j = 0; j < 4; j++) c[n][j] = 0.f;

        for (int ks = 0; ks < 8; ks++) {
            CP_WAIT(1);
            __syncthreads();
            const char* bp = smc + (ks & 1) * V_PBUF;
            const uint32_t xb32 = sb + (ks & 1) * V_PBUF + V_XO + xoff;

#pragma unroll
            for (int kk = 0; kk < 2; kk++) {
                const char* wr = bp + (16 * w + g) * PW + kk * 64 + c4 * 8;
                float2 p00 = *(const float2*)wr;
                float2 p10 = *(const float2*)(wr + 8 * PW);
                float2 p01 = *(const float2*)(wr + 32);
                float2 p11 = *(const float2*)(wr + 8 * PW + 32);
                uint32_t ah[4], al[4];
                split_pack(p00, ah[0], al[0]);
                split_pack(p10, ah[1], al[1]);
                split_pack(p01, ah[2], al[2]);
                split_pack(p11, ah[3], al[3]);
#pragma unroll
                for (int nf = 0; nf < 8; nf += 2) {
                    uint32_t bh[4], bl[4];
                    uint32_t a = xb32 + kk * (16 * PX) + nf * 16;
                    ldsm_x4t(bh, a);
                    ldsm_x4t(bl, a + (V_XLO - V_XO));
                    mma16816(c[nf], ah, bh[0], bh[1]);
                    mma16816(c[nf], ah, bl[0], bl[1]);
                    mma16816(c[nf], al, bh[0], bh[1]);
                    mma16816(c[nf + 1], ah, bh[2], bh[3]);
                    mma16816(c[nf + 1], ah, bl[2], bl[3]);
                    mma16816(c[nf + 1], al, bh[2], bh[3]);
                }
            }
            __syncthreads();
            if (ks + 2 < 8) issue(ks + 2, ks & 1);
            else CP_COMMIT();
        }

        const float b0 = bv[m0 + 16 * w + g];
        const float b1 = bv[m0 + 16 * w + g + 8];
        __syncthreads();
        __half* st = (__half*)smc;
#pragma unroll
        for (int nf = 0; nf < 8; nf++) {
            int n = nf * 8 + 2 * c4;
            int m = 16 * w + g;
            st[n * 136 + m]           = __float2half_rn(c[nf][0] + b0);
            st[(n + 1) * 136 + m]     = __float2half_rn(c[nf][1] + b0);
            st[n * 136 + m + 8]       = __float2half_rn(c[nf][2] + b1);
            st[(n + 1) * 136 + m + 8] = __float2half_rn(c[nf][3] + b1);
        }
        __syncthreads();
#pragma unroll
        for (int i = 0; i < 4; i++) {
            int idx = i * 256 + tid, n = idx >> 4, cc = idx & 15;
            *(uint4*)&g_Vh[((size_t)b * N_TOK + n0 + n) * C_DIM + m0 + cc * 8] =
                *(const uint4*)&st[n * 136 + cc * 8];
        }
    } else {
        // ---------------- Q+K projection ----------------
        const int mg = w & 3, nh = w >> 2;

        auto issue = [&](int ks, int bufi) {
            const int k0 = ks * 32;
            uint32_t base = sb + bufi * Q_PBUF;
#pragma unroll
            for (int i = 0; i < 2; i++) {
                int idx = i * 256 + tid, row = idx >> 3, cc = idx & 7;
                const float* src = (row < 32)
                    ? Wq + (size_t)row * C_DIM + k0 + cc * 4
                    : Wk + (size_t)(row - 32) * C_DIM + k0 + cc * 4;
                CPASYNC(base + row * PW + cc * 16, src);
            }
            {
                int row = tid >> 3, cc = tid & 7;
                CPASYNC(base + Q_XO + row * PX + cc * 16,
                        xh + (size_t)(k0 + row) * N_TOK + cc * 8);
                CPASYNC(base + Q_XLO + row * PX + cc * 16,
                        xl + (size_t)(k0 + row) * N_TOK + cc * 8);
            }
            CP_COMMIT();
        };

        issue(0, 0);
        issue(1, 1);

        float c[4][4];
#pragma unroll
        for (int n = 0; n < 4; n++)
#pragma unroll
            for (int j = 0; j < 4; j++) c[n][j] = 0.f;

        for (int ks = 0; ks < 8; ks++) {
            CP_WAIT(1);
            __syncthreads();
            const char* bp = smc + (ks & 1) * Q_PBUF;
            const uint32_t xb32 = sb + (ks & 1) * Q_PBUF + Q_XO + xoff;

#pragma unroll
            for (int kk = 0; kk < 2; kk++) {
                const char* wr = bp + (16 * mg + g) * PW + kk * 64 + c4 * 8;
                float2 p00 = *(const float2*)wr;
                float2 p10 = *(const float2*)(wr + 8 * PW);
                float2 p01 = *(const float2*)(wr + 32);
                float2 p11 = *(const float2*)(wr + 8 * PW + 32);
                uint32_t ah[4], al[4];
                split_pack(p00, ah[0], al[0]);
                split_pack(p10, ah[1], al[1]);
                split_pack(p01, ah[2], al[2]);
                split_pack(p11, ah[3], al[3]);
#pragma unroll
                for (int j = 0; j < 4; j += 2) {
                    uint32_t bh[4], bl[4];
                    uint32_t a = xb32 + kk * (16 * PX) + (4 * nh + j) * 16;
                    ldsm_x4t(bh, a);
                    ldsm_x4t(bl, a + (Q_XLO - Q_XO));
                    mma16816(c[j], ah, bh[0], bh[1]);
                    mma16816(c[j], ah, bl[0], bl[1]);
                    mma16816(c[j], al, bh[0], bh[1]);
                    mma16816(c[j + 1], ah, bh[2], bh[3]);
                    mma16816(c[j + 1], ah, bl[2], bl[3]);
                    mma16816(c[j + 1], al, bh[2], bh[3]);
                }
            }
            __syncthreads();
            if (ks + 2 < 8) issue(ks + 2, ks & 1);
            else CP_COMMIT();
        }

        const int m = 16 * mg + g;
        const bool isQ = (mg < 2);
        const int col0 = isQ ? m : m - 32;
        const int col1 = col0 + 8;
        const float bias0 = isQ ? bq[col0] : bk[col0];
        const float bias1 = isQ ? bq[col1] : bk[col1];
        const float sc = isQ ? LOG2E : 1.f;

#pragma unroll
        for (int j = 0; j < 4; j++) {
            int n = n0 + (4 * nh + j) * 8 + 2 * c4;
            float v[4] = { (c[j][0] + bias0) * sc, (c[j][1] + bias0) * sc,
                           (c[j][2] + bias1) * sc, (c[j][3] + bias1) * sc };
            size_t i00 = ((size_t)b * N_TOK + n) * D_QK;
            size_t i01 = ((size_t)b * N_TOK + n + 1) * D_QK;
#pragma unroll
            for (int t = 0; t < 4; t++) {
                size_t di = ((t & 1) ? i01 : i00) + ((t < 2) ? col0 : col1);
                __half hv = __float2half_rn(v[t]);
                if (isQ) {
                    g_Qh[di] = hv;
                } else {
                    g_Kh[di] = hv;
                    g_Kl[di] = __float2half_rn(v[t] - __half2float(hv));
                }
            }
        }
    }
}

// ===== flash attention: R14 core + fused K hi/lo ldsm_x4 ===================
__global__ __launch_bounds__(256, 1)
void attn_hmma(float* __restrict__ out) {
    extern __shared__ char smc[];
    const uint32_t sb = smem_u32(smc);
    const int tid = threadIdx.x;
    const int w = tid >> 5, lane = tid & 31;
    const int g = lane >> 2, c4 = lane & 3;
    const int b = blockIdx.y, m0 = blockIdx.x * BLK_M;

    // ---- stage Qh tile ----
    {
        const __half* Qh = g_Qh + ((size_t)b * N_TOK + m0) * D_QK;
#pragma unroll
        for (int i = 0; i < 2; i++) {
            int idx = i * 256 + tid;
            int row = idx >> 2, cc = idx & 3;
            CPASYNC(sb + row * PAD_K + cc * 16, Qh + row * D_QK + cc * 8);
        }
        CP_COMMIT();
        CP_WAIT(0);
        __syncthreads();
    }
    uint32_t qh[2][4];
    {
        uint32_t qoff = (uint32_t)((16 * w + ((lane >> 3) & 1) * 8 + (lane & 7)) * PAD_K
                                   + (lane >> 4) * 16);
#pragma unroll
        for (int kk = 0; kk < 2; kk++)
            ldsm_x4(qh[kk], sb + qoff + kk * 32);
    }
    __syncthreads();

    const __half* Kh = g_Kh + (size_t)b * N_TOK * D_QK;
    const __half* Kl = g_Kl + (size_t)b * N_TOK * D_QK;
    const __half* Vh = g_Vh + (size_t)b * N_TOK * C_DIM;

    const int ls = lane & 15, lr = ls & 7, lsel = ls >> 3;
    // lanes 0-15 -> Kh fragments; lanes 16-31 -> Kl (same layout + KBYTES)
    const uint32_t kbx = (uint32_t)(lr * PAD_K + lsel * 16 + (lane >> 4) * KBYTES);
    const uint32_t vb = (uint32_t)(VOFF + (lsel * 8 + lr) * PAD_V + (lane >> 4) * 16);

    auto issue_tile = [&](int kt0, uint32_t bs_) {
        {
            int row = tid >> 2, cc = tid & 3;
            uint32_t dst = bs_ + row * PAD_K + cc * 16;
            CPASYNC(dst, Kh + (kt0 + row) * D_QK + cc * 8);
            CPASYNC(dst + (uint32_t)KBYTES, Kl + (kt0 + row) * D_QK + cc * 8);
        }
#pragma unroll
        for (int i = 0; i < 8; i++) {
            int idx = i * 256 + tid;
            int row = idx >> 5, cc = idx & 31;
            CPASYNC(bs_ + VOFF + row * PAD_V + cc * 16,
                    Vh + (size_t)(kt0 + row) * C_DIM + cc * 8);
        }
        CP_COMMIT();
    };

    issue_tile(0, sb + SM_BUFS);
    issue_tile(BLK_N, sb + SM_BUFS + BUF_BYTES);

    float o[32][4];
#pragma unroll
    for (int n = 0; n < 32; n++)
#pragma unroll
        for (int j = 0; j < 4; j++) o[n][j] = 0.f;
    float m2l = -1e30f, m2h = -1e30f, llo = 0.f, lhi = 0.f;

    int b3 = 0;
    for (int kt = 0; kt < NKT; kt++) {
        CP_WAIT(1);
        __syncthreads();

        int i3 = b3 + 2; if (i3 >= 3) i3 -= 3;
        if (kt + 2 < NKT)
            issue_tile((kt + 2) * BLK_N, sb + SM_BUFS + i3 * BUF_BYTES);
        else
            CP_COMMIT();

        const uint32_t bs_ = sb + SM_BUFS + b3 * BUF_BYTES;

        // ----- S = Q K^T : 2-term, fused hi/lo ldsm_x4 -----
        float sf[8][4];
#pragma unroll
        for (int n = 0; n < 8; n++)
#pragma unroll
            for (int j = 0; j < 4; j++) sf[n][j] = 0.f;

#pragma unroll
        for (int n = 0; n < 8; n++) {
#pragma unroll
            for (int kk = 0; kk < 2; kk++) {
                uint32_t kd[4];
                ldsm_x4(kd, bs_ + kbx + n * (8 * PAD_K) + kk * 32);
                mma16816(sf[n], qh[kk], kd[0], kd[1]);   // Qh * Kh
                mma16816(sf[n], qh[kk], kd[2], kd[3]);   // Qh * Kl
            }
        }

        // ----- online softmax -----
        float rml = -1e30f, rmh = -1e30f;
#pragma unroll
        for (int n = 0; n < 8; n++) {
            rml = fmaxf(rml, fmaxf(sf[n][0], sf[n][1]));
            rmh = fmaxf(rmh, fmaxf(sf[n][2], sf[n][3]));
        }
#pragma unroll
        for (int off = 1; off <= 2; off <<= 1) {
            rml = fmaxf(rml, __shfl_xor_sync(0xffffffffu, rml, off));
            rmh = fmaxf(rmh, __shfl_xor_sync(0xffffffffu, rmh, off));
        }
        float mnl = fmaxf(m2l, rml), mnh = fmaxf(m2h, rmh);
        bool ch = (mnl != m2l) || (mnh != m2h);
        if (__any_sync(0xffffffffu, ch)) {
            float sl = fast_exp2(m2l - mnl), sh = fast_exp2(m2h - mnh);
            llo *= sl; lhi *= sh;
#pragma unroll
            for (int n = 0; n < 32; n++) {
                o[n][0] *= sl; o[n][1] *= sl;
                o[n][2] *= sh; o[n][3] *= sh;
            }
        }
        m2l = mnl; m2h = mnh;

#pragma unroll
        for (int n = 0; n < 8; n++) {
            sf[n][0] = fast_exp2(sf[n][0] - mnl);
            sf[n][1] = fast_exp2(sf[n][1] - mnl);
            sf[n][2] = fast_exp2(sf[n][2] - mnh);
            sf[n][3] = fast_exp2(sf[n][3] - mnh);
            llo += sf[n][0] + sf[n][1];
            lhi += sf[n][2] + sf[n][3];
        }

        // ----- O += P V -----
#pragma unroll
        for (int kk = 0; kk < 4; kk++) {
            uint32_t pa[4];
            pa[0] = packh2(sf[2 * kk][0],     sf[2 * kk][1]);
            pa[1] = packh2(sf[2 * kk][2],     sf[2 * kk][3]);
            pa[2] = packh2(sf[2 * kk + 1][0], sf[2 * kk + 1][1]);
            pa[3] = packh2(sf[2 * kk + 1][2], sf[2 * kk + 1][3]);
            uint32_t va = bs_ + vb + kk * (16 * PAD_V);
#pragma unroll
            for (int n = 0; n < 32; n += 2) {
                uint32_t bf[4];
                ldsm_x4t(bf, va + n * 16);
                mma16816(o[n],     pa, bf[0], bf[1]);
                mma16816(o[n + 1], pa, bf[2], bf[3]);
            }
        }

        if (++b3 == 3) b3 = 0;
    }

    // ---- epilogue ----
#pragma unroll
    for (int off = 1; off <= 2; off <<= 1) {
        llo += __shfl_xor_sync(0xffffffffu, llo, off);
        lhi += __shfl_xor_sync(0xffffffffu, lhi, off);
    }
    const float il = 1.f / llo, ih = 1.f / lhi;
    const int tok_lo = m0 + 16 * w + g, tok_hi = tok_lo + 8;
    float* ob = out + (size_t)b * C_DIM * N_TOK;
#pragma unroll
    for (int n = 0; n < 32; n++) {
        int ch0 = 8 * n + 2 * c4;
        ob[(size_t)ch0 * N_TOK + tok_lo]       = o[n][0] * il;
        ob[(size_t)(ch0 + 1) * N_TOK + tok_lo] = o[n][1] * il;
        ob[(size_t)ch0 * N_TOK + tok_hi]       = o[n][2] * ih;
        ob[(size_t)(ch0 + 1) * N_TOK + tok_hi] = o[n][3] * ih;
    }
}

// ---------------- launch ----------------
extern "C" void kernel_launch(void* const* d_in, const int* in_sizes, int n_in,
                              void* d_out, int out_size) {
    (void)in_sizes; (void)n_in; (void)out_size;
    const float* x  = (const float*)d_in[0];
    const float* Wq = (const float*)d_in[1];
    const float* bq = (const float*)d_in[2];
    const float* Wk = (const float*)d_in[3];
    const float* bk = (const float*)d_in[4];
    const float* Wv = (const float*)d_in[5];
    const float* bv = (const float*)d_in[6];
    float* out = (float*)d_out;

    cudaFuncSetAttribute(attn_hmma, cudaFuncAttributeMaxDynamicSharedMemorySize,
                         SM_ATTN);
    cudaFuncSetAttribute(proj_fused, cudaFuncAttributeMaxDynamicSharedMemorySize,
                         SM_PROJ);

    cvt_x<<<1024, 256>>>(x);

    dim3 gp(N_TOK / 64, 3, BATCH);
    proj_fused<<<gp, 256, SM_PROJ>>>(Wq, bq, Wk, bk, Wv, bv);

    dim3 ga(N_TOK / BLK_M, BATCH);
    attn_hmma<<<ga, 256, SM_ATTN>>>(out);
}